// round 14
// baseline (speedup 1.0000x reference)
#include <cuda_runtime.h>
#include <cstdint>

// Problem constants (fixed shapes per reference)
#define NN 50000
#define EE 800000
#define IN_F 128
#define KTOP 32

// Scratch (static device globals: allocation-free)
__device__ int   g_deg[NN];
__device__ int   g_rowptr[NN + 1];
__device__ int   g_cursor[NN];
__device__ int   g_csrc[EE];
__device__ float g_y[(size_t)NN * IN_F];       // y = x_sparse @ W_neigh
__device__ float g_hneigh[(size_t)NN * IN_F];  // averaged neighbor sum

// ---------------------------------------------------------------------------
// Kernel 1: zero deg
// ---------------------------------------------------------------------------
__global__ void k_zero_deg() {
    int i = blockIdx.x * blockDim.x + threadIdx.x;
    if (i < NN) g_deg[i] = 0;
}

// ---------------------------------------------------------------------------
// Kernel 2: in-degree histogram over dst (4 edges/thread, vectorized load)
// ---------------------------------------------------------------------------
__global__ void k_deg(const int* __restrict__ dst) {
    int i = blockIdx.x * blockDim.x + threadIdx.x;   // int4 index
    if (i * 4 + 3 < EE) {
        int4 d = reinterpret_cast<const int4*>(dst)[i];
        atomicAdd(&g_deg[d.x], 1);
        atomicAdd(&g_deg[d.y], 1);
        atomicAdd(&g_deg[d.z], 1);
        atomicAdd(&g_deg[d.w], 1);
    } else {
        for (int j = i * 4; j < EE; j++) atomicAdd(&g_deg[dst[j]], 1);
    }
}

// ---------------------------------------------------------------------------
// Kernel 3: single-block exclusive prefix scan of deg -> rowptr (+cursor copy)
// ---------------------------------------------------------------------------
#define SCAN_T 1024
#define SCAN_CH 49

__global__ __launch_bounds__(SCAN_T)
void k_scan() {
    __shared__ int sums[SCAN_T];
    int t = threadIdx.x;
    int base = t * SCAN_CH;

    int s = 0;
    #pragma unroll 7
    for (int i = 0; i < SCAN_CH; i++) {
        int j = base + i;
        if (j < NN) s += g_deg[j];
    }
    sums[t] = s;
    __syncthreads();

    for (int off = 1; off < SCAN_T; off <<= 1) {
        int tmp = 0;
        if (t >= off) tmp = sums[t - off];
        __syncthreads();
        if (t >= off) sums[t] += tmp;
        __syncthreads();
    }
    int run = sums[t] - s;

    #pragma unroll 7
    for (int i = 0; i < SCAN_CH; i++) {
        int j = base + i;
        if (j < NN) {
            g_rowptr[j] = run;
            g_cursor[j] = run;
            run += g_deg[j];
        }
    }
    if (t == 0) g_rowptr[NN] = EE;
}

// ---------------------------------------------------------------------------
// Kernel 4: fill CSR src lists (order within node arbitrary). 2 edges/thread.
// ---------------------------------------------------------------------------
__global__ void k_fill(const int* __restrict__ src, const int* __restrict__ dst) {
    int i = blockIdx.x * blockDim.x + threadIdx.x;   // int2 index
    if (i * 2 + 1 < EE) {
        int2 d = reinterpret_cast<const int2*>(dst)[i];
        int2 s = reinterpret_cast<const int2*>(src)[i];
        int p0 = atomicAdd(&g_cursor[d.x], 1);
        int p1 = atomicAdd(&g_cursor[d.y], 1);
        g_csrc[p0] = s.x;
        g_csrc[p1] = s.y;
    } else {
        for (int j = i * 2; j < EE; j++) {
            int pos = atomicAdd(&g_cursor[dst[j]], 1);
            g_csrc[pos] = src[j];
        }
    }
}

// ---------------------------------------------------------------------------
// Kernel 5: y[s] = x_sparse[s] @ W_neigh — one warp per node, all 128 cols in
// one pass. Dedup'd (v,ix) staged in smem; W_neigh (64KB) served from L1.
// ---------------------------------------------------------------------------
#define SG_WARPS 8

__global__ __launch_bounds__(256)
void k_sparse_gemm(const float* __restrict__ topk_values,
                   const int*   __restrict__ topk_indices,
                   const float* __restrict__ Wneigh) {
    __shared__ float s_v[SG_WARPS][KTOP];
    __shared__ int   s_ix[SG_WARPS][KTOP];
    const int w    = threadIdx.x >> 5;
    const int lane = threadIdx.x & 31;
    const int node = blockIdx.x * SG_WARPS + w;
    if (node >= NN) return;

    float v  = topk_values[(size_t)node * KTOP + lane];
    int   ix = topk_indices[(size_t)node * KTOP + lane];
    unsigned peers = __match_any_sync(0xffffffffu, ix);
    if (lane != (31 - __clz(peers))) v = 0.f;      // last-wins dedup
    s_v[w][lane]  = v;
    s_ix[w][lane] = ix;
    __syncwarp();

    float4 acc = make_float4(0.f, 0.f, 0.f, 0.f);
    #pragma unroll 8
    for (int k = 0; k < KTOP; k++) {
        float vk = s_v[w][k];                      // broadcast LDS
        int   ik = s_ix[w][k];                     // broadcast LDS
        float4 wv = __ldg(reinterpret_cast<const float4*>(
                        Wneigh + (size_t)ik * IN_F + lane * 4));
        acc.x = fmaf(vk, wv.x, acc.x);
        acc.y = fmaf(vk, wv.y, acc.y);
        acc.z = fmaf(vk, wv.z, acc.z);
        acc.w = fmaf(vk, wv.w, acc.w);
    }
    *reinterpret_cast<float4*>(g_y + (size_t)node * IN_F + lane * 4) = acc;
}

// ---------------------------------------------------------------------------
// Kernel 6: g_hneigh[d] = (1/max(deg,1)) * sum_{e: dst=d} y[src_e]
// Independent of out -> can run concurrently with k_gemm_self.
// ---------------------------------------------------------------------------
__global__ __launch_bounds__(256)
void k_gather_h() {
    const int w    = threadIdx.x >> 5;
    const int lane = threadIdx.x & 31;
    const int node = blockIdx.x * 8 + w;
    if (node >= NN) return;

    const int beg = g_rowptr[node];
    const int end = g_rowptr[node + 1];
    const float4* y4 = reinterpret_cast<const float4*>(g_y);

    float4 a0 = make_float4(0.f, 0.f, 0.f, 0.f);
    float4 a1 = make_float4(0.f, 0.f, 0.f, 0.f);
    float4 a2 = make_float4(0.f, 0.f, 0.f, 0.f);
    float4 a3 = make_float4(0.f, 0.f, 0.f, 0.f);

    int e = beg;
    for (; e + 3 < end; e += 4) {
        int s0 = g_csrc[e + 0];
        int s1 = g_csrc[e + 1];
        int s2 = g_csrc[e + 2];
        int s3 = g_csrc[e + 3];
        float4 v0 = y4[(size_t)s0 * 32 + lane];
        float4 v1 = y4[(size_t)s1 * 32 + lane];
        float4 v2 = y4[(size_t)s2 * 32 + lane];
        float4 v3 = y4[(size_t)s3 * 32 + lane];
        a0.x += v0.x; a0.y += v0.y; a0.z += v0.z; a0.w += v0.w;
        a1.x += v1.x; a1.y += v1.y; a1.z += v1.z; a1.w += v1.w;
        a2.x += v2.x; a2.y += v2.y; a2.z += v2.z; a2.w += v2.w;
        a3.x += v3.x; a3.y += v3.y; a3.z += v3.z; a3.w += v3.w;
    }
    for (; e < end; e++) {
        int s0 = g_csrc[e];
        float4 v0 = y4[(size_t)s0 * 32 + lane];
        a0.x += v0.x; a0.y += v0.y; a0.z += v0.z; a0.w += v0.w;
    }

    float winv = 1.0f / fmaxf((float)(end - beg), 1.0f);
    float4 r;
    r.x = (a0.x + a1.x + a2.x + a3.x) * winv;
    r.y = (a0.y + a1.y + a2.y + a3.y) * winv;
    r.z = (a0.z + a1.z + a2.z + a3.z) * winv;
    r.w = (a0.w + a1.w + a2.w + a3.w) * winv;
    *reinterpret_cast<float4*>(g_hneigh + (size_t)node * IN_F + lane * 4) = r;
}

// ---------------------------------------------------------------------------
// Kernel 7: out += g_hneigh  (streaming join, float4 grid-stride)
// ---------------------------------------------------------------------------
__global__ __launch_bounds__(256)
void k_add(float* __restrict__ out) {
    size_t i = (size_t)blockIdx.x * blockDim.x + threadIdx.x;
    const size_t total4 = (size_t)NN * IN_F / 4;
    if (i < total4) {
        float4 a = reinterpret_cast<const float4*>(out)[i];
        float4 b = reinterpret_cast<const float4*>(g_hneigh)[i];
        a.x += b.x; a.y += b.y; a.z += b.z; a.w += b.w;
        reinterpret_cast<float4*>(out)[i] = a;
    }
}

// ---------------------------------------------------------------------------
// Kernel 8: out = feat @ W_self + b_self   (M=NN, N=128, K=128)
// Tensor-core 3xTF32, hi/lo pre-split into smem at tile load (R10 version).
// ---------------------------------------------------------------------------
#define BM 128
#define BN 128
#define BK 16
#define APAD 136

__device__ __forceinline__ void split_tf32(float x, uint32_t& hi, uint32_t& lo) {
    uint32_t h;
    asm("cvt.rna.tf32.f32 %0, %1;" : "=r"(h) : "f"(x));
    float lf = x - __uint_as_float(h);
    uint32_t l;
    asm("cvt.rna.tf32.f32 %0, %1;" : "=r"(l) : "f"(lf));
    hi = h; lo = l;
}

__device__ __forceinline__ void mma_tf32(float* d, const uint32_t* a,
                                         uint32_t b0, uint32_t b1) {
    asm volatile(
        "mma.sync.aligned.m16n8k8.row.col.f32.tf32.tf32.f32 "
        "{%0,%1,%2,%3}, {%4,%5,%6,%7}, {%8,%9}, {%0,%1,%2,%3};"
        : "+f"(d[0]), "+f"(d[1]), "+f"(d[2]), "+f"(d[3])
        : "r"(a[0]), "r"(a[1]), "r"(a[2]), "r"(a[3]), "r"(b0), "r"(b1));
}

__global__ __launch_bounds__(256, 2)
void k_gemm_self(const float* __restrict__ feat,
                 const float* __restrict__ Wself,
                 const float* __restrict__ bself,
                 float* __restrict__ out) {
    __shared__ uint32_t As_hi[BK][APAD], As_lo[BK][APAD];   // [k][m]
    __shared__ uint32_t Bs_hi[BK][APAD], Bs_lo[BK][APAD];   // [k][n]

    const int t    = threadIdx.x;
    const int m0   = blockIdx.x * BM;
    const int wid  = t >> 5;
    const int lane = t & 31;
    const int wm   = wid & 3;
    const int wn   = wid >> 2;
    const int grp  = lane >> 2;
    const int tig  = lane & 3;

    float acc[2][8][4];
    #pragma unroll
    for (int mi = 0; mi < 2; mi++)
        #pragma unroll
        for (int ni = 0; ni < 8; ni++)
            #pragma unroll
            for (int r = 0; r < 4; r++) acc[mi][ni][r] = 0.f;

    for (int kc = 0; kc < IN_F; kc += BK) {
        #pragma unroll
        for (int l = 0; l < 2; l++) {
            int f4  = t + l * 256;
            int row = f4 >> 2;
            int kq  = f4 & 3;
            int gr  = m0 + row;
            float4 v = make_float4(0.f, 0.f, 0.f, 0.f);
            if (gr < NN)
                v = *reinterpret_cast<const float4*>(
                        feat + (size_t)gr * IN_F + kc + kq * 4);
            uint32_t h, lo;
            split_tf32(v.x, h, lo); As_hi[kq*4+0][row] = h; As_lo[kq*4+0][row] = lo;
            split_tf32(v.y, h, lo); As_hi[kq*4+1][row] = h; As_lo[kq*4+1][row] = lo;
            split_tf32(v.z, h, lo); As_hi[kq*4+2][row] = h; As_lo[kq*4+2][row] = lo;
            split_tf32(v.w, h, lo); As_hi[kq*4+3][row] = h; As_lo[kq*4+3][row] = lo;
        }
        #pragma unroll
        for (int l = 0; l < 2; l++) {
            int f4 = t + l * 256;
            int kr = f4 >> 5;
            int nq = f4 & 31;
            float4 v = *reinterpret_cast<const float4*>(
                           Wself + (size_t)(kc + kr) * 128 + nq * 4);
            uint32_t h, lo;
            split_tf32(v.x, h, lo); Bs_hi[kr][nq*4+0] = h; Bs_lo[kr][nq*4+0] = lo;
            split_tf32(v.y, h, lo); Bs_hi[kr][nq*4+1] = h; Bs_lo[kr][nq*4+1] = lo;
            split_tf32(v.z, h, lo); Bs_hi[kr][nq*4+2] = h; Bs_lo[kr][nq*4+2] = lo;
            split_tf32(v.w, h, lo); Bs_hi[kr][nq*4+3] = h; Bs_lo[kr][nq*4+3] = lo;
        }
        __syncthreads();

        #pragma unroll
        for (int ks = 0; ks < BK; ks += 8) {
            uint32_t ah[2][4], al[2][4];
            #pragma unroll
            for (int mi = 0; mi < 2; mi++) {
                int r0 = wm * 32 + mi * 16 + grp;
                ah[mi][0] = As_hi[ks + tig    ][r0    ];
                ah[mi][1] = As_hi[ks + tig    ][r0 + 8];
                ah[mi][2] = As_hi[ks + tig + 4][r0    ];
                ah[mi][3] = As_hi[ks + tig + 4][r0 + 8];
                al[mi][0] = As_lo[ks + tig    ][r0    ];
                al[mi][1] = As_lo[ks + tig    ][r0 + 8];
                al[mi][2] = As_lo[ks + tig + 4][r0    ];
                al[mi][3] = As_lo[ks + tig + 4][r0 + 8];
            }
            #pragma unroll
            for (int ni = 0; ni < 8; ni++) {
                int c = wn * 64 + ni * 8 + grp;
                uint32_t bh0 = Bs_hi[ks + tig    ][c];
                uint32_t bh1 = Bs_hi[ks + tig + 4][c];
                uint32_t bl0 = Bs_lo[ks + tig    ][c];
                uint32_t bl1 = Bs_lo[ks + tig + 4][c];
                #pragma unroll
                for (int mi = 0; mi < 2; mi++) {
                    mma_tf32(acc[mi][ni], ah[mi], bh0, bh1);
                    mma_tf32(acc[mi][ni], ah[mi], bl0, bl1);
                    mma_tf32(acc[mi][ni], al[mi], bh0, bh1);
                }
            }
        }
        __syncthreads();
    }

    #pragma unroll
    for (int mi = 0; mi < 2; mi++) {
        int rbase = m0 + wm * 32 + mi * 16 + grp;
        #pragma unroll
        for (int ni = 0; ni < 8; ni++) {
            int c = wn * 64 + ni * 8 + tig * 2;
            float bx = bself[c], by = bself[c + 1];
            if (rbase < NN) {
                float2 v0 = make_float2(acc[mi][ni][0] + bx, acc[mi][ni][1] + by);
                *reinterpret_cast<float2*>(out + (size_t)rbase * IN_F + c) = v0;
            }
            if (rbase + 8 < NN) {
                float2 v1 = make_float2(acc[mi][ni][2] + bx, acc[mi][ni][3] + by);
                *reinterpret_cast<float2*>(out + (size_t)(rbase + 8) * IN_F + c) = v1;
            }
        }
    }
}

// ---------------------------------------------------------------------------
// Launch: overlap complementary-resource kernels.
//   s0: sparse_gemm -> gemm_self ............ L1/tensor path
//   s1: zero->deg->scan->fill -> gather_h ... L2/atomic path (gather needs evY)
//   join: out += hneigh (k_add on s0 after evH)
// Host launch order keeps gemm_self at profiled slot 4.
// ---------------------------------------------------------------------------
extern "C" void kernel_launch(void* const* d_in, const int* in_sizes, int n_in,
                              void* d_out, int out_size) {
    const float* feat   = (const float*)d_in[0];
    const float* tkv    = (const float*)d_in[1];
    const int*   tki    = (const int*)  d_in[2];
    const int*   src    = (const int*)  d_in[3];
    const int*   dst    = (const int*)  d_in[4];
    const float* Wself  = (const float*)d_in[5];
    const float* bself  = (const float*)d_in[6];
    const float* Wneigh = (const float*)d_in[7];
    float* out = (float*)d_out;

    static cudaStream_t s1 = nullptr;
    static cudaEvent_t evRoot = nullptr, evY = nullptr, evH = nullptr;
    if (s1 == nullptr) {
        cudaStreamCreateWithFlags(&s1, cudaStreamNonBlocking);
        cudaEventCreateWithFlags(&evRoot, cudaEventDisableTiming);
        cudaEventCreateWithFlags(&evY,    cudaEventDisableTiming);
        cudaEventCreateWithFlags(&evH,    cudaEventDisableTiming);
    }

    // Fork CSR branch off the default stream
    cudaEventRecord(evRoot, 0);
    cudaStreamWaitEvent(s1, evRoot, 0);

    k_sparse_gemm<<<(NN + SG_WARPS - 1) / SG_WARPS, 256>>>(tkv, tki, Wneigh); // 1 (s0)
    cudaEventRecord(evY, 0);

    k_zero_deg<<<(NN + 255) / 256, 256, 0, s1>>>();                 // 2 (s1)
    k_deg<<<(EE / 4 + 255) / 256, 256, 0, s1>>>(dst);               // 3 (s1)

    k_gemm_self<<<(NN + BM - 1) / BM, 256>>>(feat, Wself, bself, out); // 4 (s0, profiled)

    k_scan<<<1, SCAN_T, 0, s1>>>();                                 // 5 (s1)
    k_fill<<<(EE / 2 + 255) / 256, 256, 0, s1>>>(src, dst);         // 6 (s1)

    // gather needs csr (same stream) + y (evY)
    cudaStreamWaitEvent(s1, evY, 0);
    k_gather_h<<<(NN + 7) / 8, 256, 0, s1>>>();                     // 7 (s1)
    cudaEventRecord(evH, s1);

    // Join: out += hneigh (s0 already ordered after gemm_self)
    cudaStreamWaitEvent(0, evH, 0);
    k_add<<<(NN * IN_F / 4 + 255) / 256, 256>>>(out);               // 8 (s0)
}

// round 16
// speedup vs baseline: 1.2616x; 1.2616x over previous
#include <cuda_runtime.h>
#include <cstdint>

// Problem constants (fixed shapes per reference)
#define NN 50000
#define EE 800000
#define IN_F 128
#define KTOP 32

// Scratch (static device globals: allocation-free)
__device__ int   g_deg[NN];
__device__ int   g_rowptr[NN + 1];
__device__ int   g_cursor[NN];
__device__ int   g_csrc[EE];
__device__ float g_y[(size_t)NN * IN_F];       // y = x_sparse @ W_neigh

// ---------------------------------------------------------------------------
// Kernel 1: zero deg
// ---------------------------------------------------------------------------
__global__ void k_zero_deg() {
    int i = blockIdx.x * blockDim.x + threadIdx.x;
    if (i < NN) g_deg[i] = 0;
}

// ---------------------------------------------------------------------------
// Kernel 2: in-degree histogram over dst (4 edges/thread, vectorized load)
// ---------------------------------------------------------------------------
__global__ void k_deg(const int* __restrict__ dst) {
    int i = blockIdx.x * blockDim.x + threadIdx.x;   // int4 index
    if (i * 4 + 3 < EE) {
        int4 d = reinterpret_cast<const int4*>(dst)[i];
        atomicAdd(&g_deg[d.x], 1);
        atomicAdd(&g_deg[d.y], 1);
        atomicAdd(&g_deg[d.z], 1);
        atomicAdd(&g_deg[d.w], 1);
    } else {
        for (int j = i * 4; j < EE; j++) atomicAdd(&g_deg[dst[j]], 1);
    }
}

// ---------------------------------------------------------------------------
// Kernel 3: single-block exclusive prefix scan of deg -> rowptr (+cursor copy)
// ---------------------------------------------------------------------------
#define SCAN_T 1024
#define SCAN_CH 49

__global__ __launch_bounds__(SCAN_T)
void k_scan() {
    __shared__ int sums[SCAN_T];
    int t = threadIdx.x;
    int base = t * SCAN_CH;

    int s = 0;
    #pragma unroll 7
    for (int i = 0; i < SCAN_CH; i++) {
        int j = base + i;
        if (j < NN) s += g_deg[j];
    }
    sums[t] = s;
    __syncthreads();

    for (int off = 1; off < SCAN_T; off <<= 1) {
        int tmp = 0;
        if (t >= off) tmp = sums[t - off];
        __syncthreads();
        if (t >= off) sums[t] += tmp;
        __syncthreads();
    }
    int run = sums[t] - s;

    #pragma unroll 7
    for (int i = 0; i < SCAN_CH; i++) {
        int j = base + i;
        if (j < NN) {
            g_rowptr[j] = run;
            g_cursor[j] = run;
            run += g_deg[j];
        }
    }
    if (t == 0) g_rowptr[NN] = EE;
}

// ---------------------------------------------------------------------------
// Kernel 4: fill CSR src lists (order within node arbitrary). 2 edges/thread.
// ---------------------------------------------------------------------------
__global__ void k_fill(const int* __restrict__ src, const int* __restrict__ dst) {
    int i = blockIdx.x * blockDim.x + threadIdx.x;   // int2 index
    if (i * 2 + 1 < EE) {
        int2 d = reinterpret_cast<const int2*>(dst)[i];
        int2 s = reinterpret_cast<const int2*>(src)[i];
        int p0 = atomicAdd(&g_cursor[d.x], 1);
        int p1 = atomicAdd(&g_cursor[d.y], 1);
        g_csrc[p0] = s.x;
        g_csrc[p1] = s.y;
    } else {
        for (int j = i * 2; j < EE; j++) {
            int pos = atomicAdd(&g_cursor[dst[j]], 1);
            g_csrc[pos] = src[j];
        }
    }
}

// ---------------------------------------------------------------------------
// Kernel 5: y[s] = x_sparse[s] @ W_neigh — one warp per node, all 128 cols in
// one pass. Dedup'd (v,ix) staged in smem; W_neigh (64KB) served from L1.
// ---------------------------------------------------------------------------
#define SG_WARPS 8

__global__ __launch_bounds__(256)
void k_sparse_gemm(const float* __restrict__ topk_values,
                   const int*   __restrict__ topk_indices,
                   const float* __restrict__ Wneigh) {
    __shared__ float s_v[SG_WARPS][KTOP];
    __shared__ int   s_ix[SG_WARPS][KTOP];
    const int w    = threadIdx.x >> 5;
    const int lane = threadIdx.x & 31;
    const int node = blockIdx.x * SG_WARPS + w;
    if (node >= NN) return;

    float v  = topk_values[(size_t)node * KTOP + lane];
    int   ix = topk_indices[(size_t)node * KTOP + lane];
    unsigned peers = __match_any_sync(0xffffffffu, ix);
    if (lane != (31 - __clz(peers))) v = 0.f;      // last-wins dedup
    s_v[w][lane]  = v;
    s_ix[w][lane] = ix;
    __syncwarp();

    float4 acc = make_float4(0.f, 0.f, 0.f, 0.f);
    #pragma unroll 8
    for (int k = 0; k < KTOP; k++) {
        float vk = s_v[w][k];                      // broadcast LDS
        int   ik = s_ix[w][k];                     // broadcast LDS
        float4 wv = __ldg(reinterpret_cast<const float4*>(
                        Wneigh + (size_t)ik * IN_F + lane * 4));
        acc.x = fmaf(vk, wv.x, acc.x);
        acc.y = fmaf(vk, wv.y, acc.y);
        acc.z = fmaf(vk, wv.z, acc.z);
        acc.w = fmaf(vk, wv.w, acc.w);
    }
    *reinterpret_cast<float4*>(g_y + (size_t)node * IN_F + lane * 4) = acc;
}

// ---------------------------------------------------------------------------
// Kernel 6: out[d] += (1/max(deg,1)) * sum_{e: dst=d} y[src_e]
// One warp per dst node; non-atomic += into out (row owned by one warp).
// ---------------------------------------------------------------------------
__global__ __launch_bounds__(256)
void k_gather_add(float* __restrict__ out) {
    const int w    = threadIdx.x >> 5;
    const int lane = threadIdx.x & 31;
    const int node = blockIdx.x * 8 + w;
    if (node >= NN) return;

    const int beg = g_rowptr[node];
    const int end = g_rowptr[node + 1];
    const float4* y4 = reinterpret_cast<const float4*>(g_y);

    float4 a0 = make_float4(0.f, 0.f, 0.f, 0.f);
    float4 a1 = make_float4(0.f, 0.f, 0.f, 0.f);
    float4 a2 = make_float4(0.f, 0.f, 0.f, 0.f);
    float4 a3 = make_float4(0.f, 0.f, 0.f, 0.f);

    int e = beg;
    for (; e + 3 < end; e += 4) {
        int s0 = g_csrc[e + 0];
        int s1 = g_csrc[e + 1];
        int s2 = g_csrc[e + 2];
        int s3 = g_csrc[e + 3];
        float4 v0 = y4[(size_t)s0 * 32 + lane];
        float4 v1 = y4[(size_t)s1 * 32 + lane];
        float4 v2 = y4[(size_t)s2 * 32 + lane];
        float4 v3 = y4[(size_t)s3 * 32 + lane];
        a0.x += v0.x; a0.y += v0.y; a0.z += v0.z; a0.w += v0.w;
        a1.x += v1.x; a1.y += v1.y; a1.z += v1.z; a1.w += v1.w;
        a2.x += v2.x; a2.y += v2.y; a2.z += v2.z; a2.w += v2.w;
        a3.x += v3.x; a3.y += v3.y; a3.z += v3.z; a3.w += v3.w;
    }
    for (; e < end; e++) {
        int s0 = g_csrc[e];
        float4 v0 = y4[(size_t)s0 * 32 + lane];
        a0.x += v0.x; a0.y += v0.y; a0.z += v0.z; a0.w += v0.w;
    }

    float winv = 1.0f / fmaxf((float)(end - beg), 1.0f);
    float* op = out + (size_t)node * IN_F + lane * 4;
    float4 cur = *reinterpret_cast<const float4*>(op);
    float4 r;
    r.x = cur.x + (a0.x + a1.x + a2.x + a3.x) * winv;
    r.y = cur.y + (a0.y + a1.y + a2.y + a3.y) * winv;
    r.z = cur.z + (a0.z + a1.z + a2.z + a3.z) * winv;
    r.w = cur.w + (a0.w + a1.w + a2.w + a3.w) * winv;
    *reinterpret_cast<float4*>(op) = r;
}

// ---------------------------------------------------------------------------
// Kernel 7: out = feat @ W_self + b_self   (M=NN, N=128, K=128)
// Tensor-core 3xTF32, R6 variant: raw fp32 tiles in smem (17KB), hi/lo split
// done per-fragment in the mainloop (cvt ALU overlaps the tensor pipe).
// Profiled fastest of all gemm variants tried: 42.3us, tensor 38.6%.
// ---------------------------------------------------------------------------
#define BM 128
#define BN 128
#define BK 16
#define APAD 132

__device__ __forceinline__ void split_tf32(float x, uint32_t& hi, uint32_t& lo) {
    uint32_t h;
    asm("cvt.rna.tf32.f32 %0, %1;" : "=r"(h) : "f"(x));
    float lf = x - __uint_as_float(h);
    uint32_t l;
    asm("cvt.rna.tf32.f32 %0, %1;" : "=r"(l) : "f"(lf));
    hi = h; lo = l;
}

__device__ __forceinline__ void mma_tf32(float* d, const uint32_t* a,
                                         uint32_t b0, uint32_t b1) {
    asm volatile(
        "mma.sync.aligned.m16n8k8.row.col.f32.tf32.tf32.f32 "
        "{%0,%1,%2,%3}, {%4,%5,%6,%7}, {%8,%9}, {%0,%1,%2,%3};"
        : "+f"(d[0]), "+f"(d[1]), "+f"(d[2]), "+f"(d[3])
        : "r"(a[0]), "r"(a[1]), "r"(a[2]), "r"(a[3]), "r"(b0), "r"(b1));
}

__global__ __launch_bounds__(256, 2)
void k_gemm_self(const float* __restrict__ feat,
                 const float* __restrict__ Wself,
                 const float* __restrict__ bself,
                 float* __restrict__ out) {
    __shared__ float As[BK][APAD];   // [k][m]
    __shared__ float Bs[BK][BN];     // [k][n]

    const int t    = threadIdx.x;
    const int m0   = blockIdx.x * BM;
    const int wid  = t >> 5;
    const int lane = t & 31;
    const int wm   = wid & 3;        // m offset wm*32
    const int wn   = wid >> 2;       // n offset wn*64
    const int grp  = lane >> 2;      // 0..7
    const int tig  = lane & 3;       // 0..3

    float acc[2][8][4];
    #pragma unroll
    for (int mi = 0; mi < 2; mi++)
        #pragma unroll
        for (int ni = 0; ni < 8; ni++)
            #pragma unroll
            for (int r = 0; r < 4; r++) acc[mi][ni][r] = 0.f;

    for (int kc = 0; kc < IN_F; kc += BK) {
        // Load A tile (transposed to [k][m]): 128 rows x 16 k, 2 float4/thread
        #pragma unroll
        for (int l = 0; l < 2; l++) {
            int f4  = t + l * 256;
            int row = f4 >> 2;
            int kq  = f4 & 3;
            int gr  = m0 + row;
            float4 v = make_float4(0.f, 0.f, 0.f, 0.f);
            if (gr < NN)
                v = *reinterpret_cast<const float4*>(
                        feat + (size_t)gr * IN_F + kc + kq * 4);
            As[kq * 4 + 0][row] = v.x;
            As[kq * 4 + 1][row] = v.y;
            As[kq * 4 + 2][row] = v.z;
            As[kq * 4 + 3][row] = v.w;
        }
        // Load B tile [k][n]: 16 k x 128 n, 2 float4/thread
        #pragma unroll
        for (int l = 0; l < 2; l++) {
            int f4 = t + l * 256;
            int kr = f4 >> 5;
            int nq = f4 & 31;
            float4 v = *reinterpret_cast<const float4*>(
                           Wself + (size_t)(kc + kr) * 128 + nq * 4);
            *reinterpret_cast<float4*>(&Bs[kr][nq * 4]) = v;
        }
        __syncthreads();

        #pragma unroll
        for (int ks = 0; ks < BK; ks += 8) {
            // A fragments (2 m16 tiles), hi/lo split in mainloop
            uint32_t ah[2][4], al[2][4];
            #pragma unroll
            for (int mi = 0; mi < 2; mi++) {
                int r0 = wm * 32 + mi * 16 + grp;
                split_tf32(As[ks + tig    ][r0    ], ah[mi][0], al[mi][0]);
                split_tf32(As[ks + tig    ][r0 + 8], ah[mi][1], al[mi][1]);
                split_tf32(As[ks + tig + 4][r0    ], ah[mi][2], al[mi][2]);
                split_tf32(As[ks + tig + 4][r0 + 8], ah[mi][3], al[mi][3]);
            }
            #pragma unroll
            for (int ni = 0; ni < 8; ni++) {
                int c = wn * 64 + ni * 8 + grp;
                uint32_t bh0, bl0, bh1, bl1;
                split_tf32(Bs[ks + tig    ][c], bh0, bl0);
                split_tf32(Bs[ks + tig + 4][c], bh1, bl1);
                #pragma unroll
                for (int mi = 0; mi < 2; mi++) {
                    mma_tf32(acc[mi][ni], ah[mi], bh0, bh1);  // hi*hi
                    mma_tf32(acc[mi][ni], ah[mi], bl0, bl1);  // hi*lo
                    mma_tf32(acc[mi][ni], al[mi], bh0, bh1);  // lo*hi
                }
            }
        }
        __syncthreads();
    }

    // Epilogue: acc c0,c1 -> (row grp, cols 2tig,2tig+1); c2,c3 -> row grp+8
    #pragma unroll
    for (int mi = 0; mi < 2; mi++) {
        int rbase = m0 + wm * 32 + mi * 16 + grp;
        #pragma unroll
        for (int ni = 0; ni < 8; ni++) {
            int c = wn * 64 + ni * 8 + tig * 2;
            float bx = bself[c], by = bself[c + 1];
            if (rbase < NN) {
                float2 v0 = make_float2(acc[mi][ni][0] + bx, acc[mi][ni][1] + by);
                *reinterpret_cast<float2*>(out + (size_t)rbase * IN_F + c) = v0;
            }
            if (rbase + 8 < NN) {
                float2 v1 = make_float2(acc[mi][ni][2] + bx, acc[mi][ni][3] + by);
                *reinterpret_cast<float2*>(out + (size_t)(rbase + 8) * IN_F + c) = v1;
            }
        }
    }
}

// ---------------------------------------------------------------------------
// Launch: R10 anti-interference schedule (best measured): CSR branch
// concurrent; gemm_self -> sparse_gemm -> gather_add serialized on stream 0.
// gemm_self at profiled slot 4.
// ---------------------------------------------------------------------------
extern "C" void kernel_launch(void* const* d_in, const int* in_sizes, int n_in,
                              void* d_out, int out_size) {
    const float* feat   = (const float*)d_in[0];
    const float* tkv    = (const float*)d_in[1];
    const int*   tki    = (const int*)  d_in[2];
    const int*   src    = (const int*)  d_in[3];
    const int*   dst    = (const int*)  d_in[4];
    const float* Wself  = (const float*)d_in[5];
    const float* bself  = (const float*)d_in[6];
    const float* Wneigh = (const float*)d_in[7];
    float* out = (float*)d_out;

    static cudaStream_t s1 = nullptr;
    static cudaEvent_t evRoot = nullptr, evCsr = nullptr;
    if (s1 == nullptr) {
        cudaStreamCreateWithFlags(&s1, cudaStreamNonBlocking);
        cudaEventCreateWithFlags(&evRoot, cudaEventDisableTiming);
        cudaEventCreateWithFlags(&evCsr,  cudaEventDisableTiming);
    }

    // Fork CSR branch
    cudaEventRecord(evRoot, 0);
    cudaStreamWaitEvent(s1, evRoot, 0);

    k_zero_deg<<<(NN + 255) / 256, 256, 0, s1>>>();                 // 1
    k_deg<<<(EE / 4 + 255) / 256, 256, 0, s1>>>(dst);               // 2
    k_scan<<<1, SCAN_T, 0, s1>>>();                                 // 3

    // Main stream: gemm_self (slot 4, profiled) then sparse_gemm — serialized
    k_gemm_self<<<(NN + BM - 1) / BM, 256>>>(feat, Wself, bself, out);   // 4

    k_fill<<<(EE / 2 + 255) / 256, 256, 0, s1>>>(src, dst);         // 5
    cudaEventRecord(evCsr, s1);

    k_sparse_gemm<<<(NN + SG_WARPS - 1) / SG_WARPS, 256>>>(tkv, tki, Wneigh); // 6

    // Join CSR, then gather+add
    cudaStreamWaitEvent(0, evCsr, 0);
    k_gather_add<<<(NN + 7) / 8, 256>>>(out);                       // 7
}